// round 1
// baseline (speedup 1.0000x reference)
#include <cuda_runtime.h>
#include <cuda_bf16.h>

// Problem constants (from reference: N_NODES=100000, K_HOPS=2, feat 128 -> out 64)
#define N_NODES 100000
#define IN_F    128
#define OUT_F   64
#define OUT_F4  (OUT_F / 4)   // 16 float4 per node row

// Scratch (allocation-free rule: __device__ globals)
__device__ int   g_deg[N_NODES];
__device__ float g_norm[N_NODES];
__device__ float g_nsq[N_NODES];
__device__ float g_g [N_NODES * OUT_F];   // projected + pre-normalized features
__device__ float g_h1[N_NODES * OUT_F];   // hop-1 accumulator

// ---------------------------------------------------------------------------
// In-degree via int atomics (1.6M spread atomics, cheap)
__global__ void deg_kernel(const int* __restrict__ dst, int E) {
    int i = blockIdx.x * blockDim.x + threadIdx.x;
    if (i < E) atomicAdd(&g_deg[dst[i]], 1);
}

// norm = deg>0 ? rsqrt(deg) : 0 ; nsq = norm^2
__global__ void norm_kernel() {
    int i = blockIdx.x * blockDim.x + threadIdx.x;
    if (i < N_NODES) {
        int d = g_deg[i];
        float nv = (d > 0) ? rsqrtf((float)d) : 0.0f;
        g_norm[i] = nv;
        g_nsq[i]  = nv * nv;
    }
}

// ---------------------------------------------------------------------------
// g = (feat @ W^T) * norm   — 100000x128 @ 128x64
// Block: 256 threads = 4 groups of 64; each group computes 4 nodes (reg-blocked).
// W transposed into smem as Ws[k*64+t] for conflict-free reads.
#define NPB 16  // nodes per block (4 groups x 4 nodes)
__global__ void gemm_kernel(const float* __restrict__ feat,
                            const float* __restrict__ weight) {
    __shared__ float Ws[IN_F * OUT_F];    // 32 KB
    __shared__ float Fs[NPB][IN_F];       // 8 KB

    int tid = threadIdx.x;
    for (int i = tid; i < IN_F * OUT_F; i += 256) {
        int t = i / IN_F, k = i % IN_F;
        Ws[k * OUT_F + t] = weight[i];    // weight is [64][128] row-major
    }
    int nodeBase = blockIdx.x * NPB;
    for (int i = tid; i < NPB * IN_F; i += 256) {
        int n = i / IN_F, k = i % IN_F;
        int node = nodeBase + n;
        Fs[n][k] = (node < N_NODES) ? feat[node * IN_F + k] : 0.0f;
    }
    __syncthreads();

    int grp = tid >> 6;          // 0..3
    int t   = tid & 63;          // output feature
    int nl  = grp * 4;           // first local node for this group

    float acc0 = 0.f, acc1 = 0.f, acc2 = 0.f, acc3 = 0.f;
#pragma unroll 8
    for (int k = 0; k < IN_F; k++) {
        float w = Ws[k * OUT_F + t];
        acc0 += Fs[nl + 0][k] * w;
        acc1 += Fs[nl + 1][k] * w;
        acc2 += Fs[nl + 2][k] * w;
        acc3 += Fs[nl + 3][k] * w;
    }
    float accs[4] = {acc0, acc1, acc2, acc3};
#pragma unroll
    for (int j = 0; j < 4; j++) {
        int node = nodeBase + nl + j;
        if (node < N_NODES)
            g_g[node * OUT_F + t] = accs[j] * g_norm[node];
    }
}

// ---------------------------------------------------------------------------
// Vectorized global reduction (sm_90+): 16B atomic add, no return.
__device__ __forceinline__ void red_v4(float4* addr, float4 v) {
    asm volatile("red.global.add.v4.f32 [%0], {%1, %2, %3, %4};"
                 :: "l"(addr), "f"(v.x), "f"(v.y), "f"(v.z), "f"(v.w)
                 : "memory");
}

// Hop 1: h1[dst] += g[src]. 16 threads (float4 lanes) per edge.
__global__ void scatter1_kernel(const int* __restrict__ src,
                                const int* __restrict__ dst, int E) {
    int idx = blockIdx.x * blockDim.x + threadIdx.x;
    int e = idx >> 4;
    int j = idx & 15;
    if (e < E) {
        int s = src[e];
        int d = dst[e];
        const float4* gp = (const float4*)g_g;
        float4 v = gp[s * OUT_F4 + j];
        red_v4(((float4*)g_h1) + d * OUT_F4 + j, v);
    }
}

// Hop 2: out[dst] += h1[src] * nsq[src]  (nsq folds post-hop1 and pre-hop2 norms)
__global__ void scatter2_kernel(const int* __restrict__ src,
                                const int* __restrict__ dst,
                                float* __restrict__ out, int E) {
    int idx = blockIdx.x * blockDim.x + threadIdx.x;
    int e = idx >> 4;
    int j = idx & 15;
    if (e < E) {
        int s = src[e];
        int d = dst[e];
        float sc = g_nsq[s];                 // broadcast across the 16 lanes
        const float4* hp = (const float4*)g_h1;
        float4 v = hp[s * OUT_F4 + j];
        v.x *= sc; v.y *= sc; v.z *= sc; v.w *= sc;
        red_v4(((float4*)out) + d * OUT_F4 + j, v);
    }
}

// Final: out = out * norm + bias  (in place)
__global__ void final_kernel(float* __restrict__ out,
                             const float* __restrict__ bias) {
    int i = blockIdx.x * blockDim.x + threadIdx.x;
    if (i < N_NODES * OUT_F) {
        int n = i / OUT_F;
        int t = i % OUT_F;
        out[i] = out[i] * g_norm[n] + bias[t];
    }
}

// ---------------------------------------------------------------------------
extern "C" void kernel_launch(void* const* d_in, const int* in_sizes, int n_in,
                              void* d_out, int out_size) {
    const int*   src    = (const int*)  d_in[0];
    const int*   dst    = (const int*)  d_in[1];
    const float* feat   = (const float*)d_in[2];
    const float* weight = (const float*)d_in[3];
    const float* bias   = (const float*)d_in[4];
    float*       out    = (float*)d_out;

    const int E = in_sizes[0];

    void *deg_ptr, *h1_ptr;
    cudaGetSymbolAddress(&deg_ptr, g_deg);
    cudaGetSymbolAddress(&h1_ptr,  g_h1);

    // Zero accumulators (memset nodes are graph-capturable)
    cudaMemsetAsync(deg_ptr, 0, N_NODES * sizeof(int));
    cudaMemsetAsync(h1_ptr,  0, N_NODES * OUT_F * sizeof(float));
    cudaMemsetAsync(d_out,   0, (size_t)out_size * sizeof(float));

    deg_kernel<<<(E + 255) / 256, 256>>>(dst, E);
    norm_kernel<<<(N_NODES + 255) / 256, 256>>>();

    gemm_kernel<<<(N_NODES + NPB - 1) / NPB, 256>>>(feat, weight);

    int scatter_threads = E * 16;
    int scatter_blocks  = (scatter_threads + 255) / 256;
    scatter1_kernel<<<scatter_blocks, 256>>>(src, dst, E);
    scatter2_kernel<<<scatter_blocks, 256>>>(src, dst, out, E);

    final_kernel<<<(N_NODES * OUT_F + 255) / 256, 256>>>(out, bias);
}

// round 2
// speedup vs baseline: 1.3009x; 1.3009x over previous
#include <cuda_runtime.h>
#include <cuda_bf16.h>

#define N_NODES 100000
#define IN_F    128
#define OUT_F   64
#define OUT_F4  (OUT_F / 4)
#define E_MAX   1600000

#define SCAN_B  1024
#define N_SCANB ((N_NODES + SCAN_B - 1) / SCAN_B)   // 98

// ------------------------- device scratch (no allocs) -----------------------
__device__ int   g_deg [N_NODES];
__device__ int   g_incl[N_NODES];       // inclusive block-scan of deg
__device__ int   g_bsum[N_SCANB];       // per-block totals
__device__ int   g_boff[N_SCANB];       // exclusive scan of block totals
__device__ int   g_off [N_NODES];       // CSR row start
__device__ int   g_cur [N_NODES];       // fill cursor
__device__ int   g_adj [E_MAX];         // CSR column (src) indices
__device__ float g_norm[N_NODES];
__device__ float g_nsq [N_NODES];
__device__ float g_g  [N_NODES * OUT_F];  // projected, pre-normalized features
__device__ float g_h1 [N_NODES * OUT_F];  // hop-1 result (scaled by nsq)

// ------------------------- degree histogram ---------------------------------
__global__ void deg_kernel(const int* __restrict__ dst, int E) {
    int i = (blockIdx.x * blockDim.x + threadIdx.x) * 4;
    if (i + 3 < E) {
        int4 d = *(const int4*)(dst + i);
        atomicAdd(&g_deg[d.x], 1);
        atomicAdd(&g_deg[d.y], 1);
        atomicAdd(&g_deg[d.z], 1);
        atomicAdd(&g_deg[d.w], 1);
    } else {
        for (int k = i; k < E; k++) atomicAdd(&g_deg[dst[k]], 1);
    }
}

__global__ void norm_kernel() {
    int i = blockIdx.x * blockDim.x + threadIdx.x;
    if (i < N_NODES) {
        int d = g_deg[i];
        float nv = (d > 0) ? rsqrtf((float)d) : 0.0f;
        g_norm[i] = nv;
        g_nsq[i]  = nv * nv;
    }
}

// ------------------------- exclusive scan (3 stages) ------------------------
__global__ void scan1_kernel() {
    __shared__ int s[SCAN_B];
    int tid = threadIdx.x;
    int i = blockIdx.x * SCAN_B + tid;
    int v = (i < N_NODES) ? g_deg[i] : 0;
    s[tid] = v;
    __syncthreads();
#pragma unroll
    for (int off = 1; off < SCAN_B; off <<= 1) {
        int t = (tid >= off) ? s[tid - off] : 0;
        __syncthreads();
        s[tid] += t;
        __syncthreads();
    }
    if (i < N_NODES) g_incl[i] = s[tid];
    if (tid == SCAN_B - 1) g_bsum[blockIdx.x] = s[tid];
}

__global__ void scan2_kernel() {
    if (threadIdx.x == 0) {
        int acc = 0;
        for (int b = 0; b < N_SCANB; b++) {
            g_boff[b] = acc;
            acc += g_bsum[b];
        }
    }
}

__global__ void scan3_kernel() {
    int i = blockIdx.x * blockDim.x + threadIdx.x;
    if (i < N_NODES) {
        int start = g_boff[i / SCAN_B] + g_incl[i] - g_deg[i];
        g_off[i] = start;
        g_cur[i] = start;
    }
}

// ------------------------- CSR fill -----------------------------------------
__global__ void fill_kernel(const int* __restrict__ src,
                            const int* __restrict__ dst, int E) {
    int e = blockIdx.x * blockDim.x + threadIdx.x;
    if (e < E) {
        int pos = atomicAdd(&g_cur[dst[e]], 1);
        g_adj[pos] = src[e];
    }
}

// ------------------------- dense GEMM g = (feat @ W^T) * norm ---------------
#define NPB 16
__global__ void gemm_kernel(const float* __restrict__ feat,
                            const float* __restrict__ weight) {
    __shared__ float Ws[IN_F * OUT_F];    // 32 KB, k-major
    __shared__ float Fs[NPB][IN_F];       // 8 KB

    int tid = threadIdx.x;
    for (int i = tid; i < IN_F * OUT_F; i += 256) {
        int t = i / IN_F, k = i % IN_F;
        Ws[k * OUT_F + t] = weight[i];
    }
    int nodeBase = blockIdx.x * NPB;
    for (int i = tid; i < NPB * IN_F; i += 256) {
        int n = i / IN_F, k = i % IN_F;
        int node = nodeBase + n;
        Fs[n][k] = (node < N_NODES) ? feat[node * IN_F + k] : 0.0f;
    }
    __syncthreads();

    int grp = tid >> 6;
    int t   = tid & 63;
    int nl  = grp * 4;

    float acc0 = 0.f, acc1 = 0.f, acc2 = 0.f, acc3 = 0.f;
#pragma unroll 8
    for (int k = 0; k < IN_F; k++) {
        float w = Ws[k * OUT_F + t];
        acc0 += Fs[nl + 0][k] * w;
        acc1 += Fs[nl + 1][k] * w;
        acc2 += Fs[nl + 2][k] * w;
        acc3 += Fs[nl + 3][k] * w;
    }
    float accs[4] = {acc0, acc1, acc2, acc3};
#pragma unroll
    for (int j = 0; j < 4; j++) {
        int node = nodeBase + nl + j;
        if (node < N_NODES)
            g_g[node * OUT_F + t] = accs[j] * g_norm[node];
    }
}

// ------------------------- gather hops --------------------------------------
// 16 threads (one float4 column each) per node; 2 nodes per warp.
// hop1: h1[n] = (sum_{s in adj(n)} g[s]) * nsq[n]
__global__ void hop1_kernel() {
    int idx = blockIdx.x * blockDim.x + threadIdx.x;
    int node = idx >> 4;
    int j    = idx & 15;
    if (node >= N_NODES) return;

    int start = g_off[node];
    int cnt   = g_deg[node];
    const float4* __restrict__ in4 = (const float4*)g_g;

    float4 acc = make_float4(0.f, 0.f, 0.f, 0.f);
#pragma unroll 4
    for (int i = 0; i < cnt; i++) {
        int s = __ldg(&g_adj[start + i]);
        float4 v = __ldg(&in4[s * OUT_F4 + j]);
        acc.x += v.x; acc.y += v.y; acc.z += v.z; acc.w += v.w;
    }
    float sc = g_nsq[node];
    acc.x *= sc; acc.y *= sc; acc.z *= sc; acc.w *= sc;
    ((float4*)g_h1)[node * OUT_F4 + j] = acc;
}

// hop2: out[n] = (sum_{s in adj(n)} h1[s]) * norm[n] + bias
__global__ void hop2_kernel(float* __restrict__ out,
                            const float* __restrict__ bias) {
    int idx = blockIdx.x * blockDim.x + threadIdx.x;
    int node = idx >> 4;
    int j    = idx & 15;
    if (node >= N_NODES) return;

    int start = g_off[node];
    int cnt   = g_deg[node];
    const float4* __restrict__ in4 = (const float4*)g_h1;

    float4 acc = make_float4(0.f, 0.f, 0.f, 0.f);
#pragma unroll 4
    for (int i = 0; i < cnt; i++) {
        int s = __ldg(&g_adj[start + i]);
        float4 v = __ldg(&in4[s * OUT_F4 + j]);
        acc.x += v.x; acc.y += v.y; acc.z += v.z; acc.w += v.w;
    }
    float sc = g_norm[node];
    float4 b = ((const float4*)bias)[j];
    float4 r;
    r.x = acc.x * sc + b.x;
    r.y = acc.y * sc + b.y;
    r.z = acc.z * sc + b.z;
    r.w = acc.w * sc + b.w;
    ((float4*)out)[node * OUT_F4 + j] = r;
}

// ----------------------------------------------------------------------------
extern "C" void kernel_launch(void* const* d_in, const int* in_sizes, int n_in,
                              void* d_out, int out_size) {
    const int*   src    = (const int*)  d_in[0];
    const int*   dst    = (const int*)  d_in[1];
    const float* feat   = (const float*)d_in[2];
    const float* weight = (const float*)d_in[3];
    const float* bias   = (const float*)d_in[4];
    float*       out    = (float*)d_out;

    const int E = in_sizes[0];

    void* deg_ptr;
    cudaGetSymbolAddress(&deg_ptr, g_deg);
    cudaMemsetAsync(deg_ptr, 0, N_NODES * sizeof(int));

    deg_kernel<<<(E / 4 + 255) / 256, 256>>>(dst, E);
    norm_kernel<<<(N_NODES + 255) / 256, 256>>>();

    scan1_kernel<<<N_SCANB, SCAN_B>>>();
    scan2_kernel<<<1, 32>>>();
    scan3_kernel<<<(N_NODES + 255) / 256, 256>>>();
    fill_kernel<<<(E + 255) / 256, 256>>>(src, dst, E);

    gemm_kernel<<<(N_NODES + NPB - 1) / NPB, 256>>>(feat, weight);

    int hop_threads = N_NODES * 16;
    int hop_blocks  = (hop_threads + 255) / 256;
    hop1_kernel<<<hop_blocks, 256>>>();
    hop2_kernel<<<hop_blocks, 256>>>(out, bias);
}

// round 3
// speedup vs baseline: 2.8140x; 2.1632x over previous
#include <cuda_runtime.h>
#include <cuda_fp16.h>

#define N_NODES 100000
#define IN_F    128
#define OUT_F   64
#define E_MAX   1600000

#define SCAN_B  1024
#define N_SCANB ((N_NODES + SCAN_B - 1) / SCAN_B)   // 98

// ------------------------- device scratch (no allocs) -----------------------
__device__ int   g_deg [N_NODES];
__device__ int   g_incl[N_NODES];
__device__ int   g_bsum[N_SCANB];
__device__ int   g_boff[N_SCANB];
__device__ int   g_off [N_NODES];
__device__ int   g_cur [N_NODES];
__device__ int   g_adj [E_MAX];
__device__ float g_norm[N_NODES];
__device__ float g_nsq [N_NODES];
// fp16 propagation storage: 64 halves = 8 uint4 per node
__device__ uint4 g_gh [N_NODES * 8];
__device__ uint4 g_h1h[N_NODES * 8];

// ------------------------- degree histogram ---------------------------------
__global__ void deg_kernel(const int* __restrict__ dst, int E) {
    int i = (blockIdx.x * blockDim.x + threadIdx.x) * 4;
    if (i + 3 < E) {
        int4 d = *(const int4*)(dst + i);
        atomicAdd(&g_deg[d.x], 1);
        atomicAdd(&g_deg[d.y], 1);
        atomicAdd(&g_deg[d.z], 1);
        atomicAdd(&g_deg[d.w], 1);
    } else {
        for (int k = i; k < E; k++) atomicAdd(&g_deg[dst[k]], 1);
    }
}

__global__ void norm_kernel() {
    int i = blockIdx.x * blockDim.x + threadIdx.x;
    if (i < N_NODES) {
        int d = g_deg[i];
        float nv = (d > 0) ? rsqrtf((float)d) : 0.0f;
        g_norm[i] = nv;
        g_nsq[i]  = nv * nv;
    }
}

// ------------------------- exclusive scan (3 stages) ------------------------
__global__ void scan1_kernel() {
    __shared__ int s[SCAN_B];
    int tid = threadIdx.x;
    int i = blockIdx.x * SCAN_B + tid;
    int v = (i < N_NODES) ? g_deg[i] : 0;
    s[tid] = v;
    __syncthreads();
#pragma unroll
    for (int off = 1; off < SCAN_B; off <<= 1) {
        int t = (tid >= off) ? s[tid - off] : 0;
        __syncthreads();
        s[tid] += t;
        __syncthreads();
    }
    if (i < N_NODES) g_incl[i] = s[tid];
    if (tid == SCAN_B - 1) g_bsum[blockIdx.x] = s[tid];
}

// parallel 128-wide scan over N_SCANB block sums
__global__ void scan2_kernel() {
    __shared__ int s[128];
    int t = threadIdx.x;
    int v = (t < N_SCANB) ? g_bsum[t] : 0;
    s[t] = v;
    __syncthreads();
#pragma unroll
    for (int off = 1; off < 128; off <<= 1) {
        int u = (t >= off) ? s[t - off] : 0;
        __syncthreads();
        s[t] += u;
        __syncthreads();
    }
    if (t < N_SCANB) g_boff[t] = s[t] - v;   // exclusive
}

__global__ void scan3_kernel() {
    int i = blockIdx.x * blockDim.x + threadIdx.x;
    if (i < N_NODES) {
        int start = g_boff[i / SCAN_B] + g_incl[i] - g_deg[i];
        g_off[i] = start;
        g_cur[i] = start;
    }
}

// ------------------------- CSR fill -----------------------------------------
__global__ void fill_kernel(const int* __restrict__ src,
                            const int* __restrict__ dst, int E) {
    int e = blockIdx.x * blockDim.x + threadIdx.x;
    if (e < E) {
        int pos = atomicAdd(&g_cur[dst[e]], 1);
        g_adj[pos] = src[e];
    }
}

// ------------------------- dense GEMM: g = (feat @ W^T) * norm (fp16 out) ---
// 64 nodes x 64 outs per block; 256 threads as 16x16; 4x4 micro-tile each.
// k-major smem, rows padded to 68 floats (16B-aligned, conflict-breaking).
#define KP 68
__global__ void gemm_kernel(const float* __restrict__ feat,
                            const float* __restrict__ weight) {
    __shared__ float Ws[IN_F * KP];   // Ws[k][out], 34.8 KB
    __shared__ float Fs[32 * KP];     // Fs[k][node] (one 32-k chunk), 8.7 KB

    int tid = threadIdx.x;
    // Load + transpose W: weight[out][k] -> Ws[k][out]
    for (int p = tid; p < OUT_F * 32; p += 256) {
        int out = p >> 5, jc = p & 31;
        float4 w = ((const float4*)weight)[out * 32 + jc];
        int k = jc * 4;
        Ws[(k + 0) * KP + out] = w.x;
        Ws[(k + 1) * KP + out] = w.y;
        Ws[(k + 2) * KP + out] = w.z;
        Ws[(k + 3) * KP + out] = w.w;
    }

    int nodeBase = blockIdx.x * 64;
    int tx = tid & 15;        // out group: outs tx*4..+3
    int ty = tid >> 4;        // node group: nodes ty*4..+3
    float acc[4][4] = {};

    for (int kc = 0; kc < IN_F; kc += 32) {
        __syncthreads();
        // Load + transpose feat chunk: feat[node][kc+k] -> Fs[k][node]
        for (int p = tid; p < 64 * 8; p += 256) {
            int n = p >> 3, jc = p & 7;
            int node = nodeBase + n;
            float4 f = (node < N_NODES)
                ? ((const float4*)feat)[node * 32 + (kc >> 2) + jc]
                : make_float4(0.f, 0.f, 0.f, 0.f);
            int k = jc * 4;
            Fs[(k + 0) * KP + n] = f.x;
            Fs[(k + 1) * KP + n] = f.y;
            Fs[(k + 2) * KP + n] = f.z;
            Fs[(k + 3) * KP + n] = f.w;
        }
        __syncthreads();
#pragma unroll
        for (int k = 0; k < 32; k++) {
            float4 fv = *(const float4*)&Fs[k * KP + ty * 4];
            float4 wv = *(const float4*)&Ws[(kc + k) * KP + tx * 4];
            float f[4] = {fv.x, fv.y, fv.z, fv.w};
            float w[4] = {wv.x, wv.y, wv.z, wv.w};
#pragma unroll
            for (int i = 0; i < 4; i++)
#pragma unroll
                for (int j = 0; j < 4; j++)
                    acc[i][j] += f[i] * w[j];
        }
    }

    uint2* out2 = (uint2*)g_gh;   // 16 uint2 per node
#pragma unroll
    for (int i = 0; i < 4; i++) {
        int node = nodeBase + ty * 4 + i;
        if (node < N_NODES) {
            float nv = g_norm[node];
            __half2 h0 = __floats2half2_rn(acc[i][0] * nv, acc[i][1] * nv);
            __half2 h1 = __floats2half2_rn(acc[i][2] * nv, acc[i][3] * nv);
            uint2 u;
            u.x = *(unsigned int*)&h0;
            u.y = *(unsigned int*)&h1;
            out2[node * 16 + tx] = u;
        }
    }
}

// ------------------------- gather hops (fp16 in, fp32 accum) ----------------
// 16 lanes per node: lane = (j in 0..7) feat quad, (half in 0..1) neighbor phase.
__device__ __forceinline__ void h2acc(unsigned int u, float2& a) {
    float2 f = __half22float2(*reinterpret_cast<__half2*>(&u));
    a.x += f.x; a.y += f.y;
}

__global__ void hop1_kernel() {
    int idx = blockIdx.x * blockDim.x + threadIdx.x;
    int node = idx >> 4;
    if (node >= N_NODES) return;
    int lane = idx & 15;
    int j = lane & 7;
    int ph = lane >> 3;

    int start = g_off[node];
    int cnt   = g_deg[node];
    float2 a0 = {0,0}, a1 = {0,0}, a2 = {0,0}, a3 = {0,0};
#pragma unroll 2
    for (int i = ph; i < cnt; i += 2) {
        int s = __ldg(&g_adj[start + i]);
        uint4 v = __ldg(&g_gh[s * 8 + j]);
        h2acc(v.x, a0); h2acc(v.y, a1); h2acc(v.z, a2); h2acc(v.w, a3);
    }
    a0.x += __shfl_xor_sync(0xffffffffu, a0.x, 8);
    a0.y += __shfl_xor_sync(0xffffffffu, a0.y, 8);
    a1.x += __shfl_xor_sync(0xffffffffu, a1.x, 8);
    a1.y += __shfl_xor_sync(0xffffffffu, a1.y, 8);
    a2.x += __shfl_xor_sync(0xffffffffu, a2.x, 8);
    a2.y += __shfl_xor_sync(0xffffffffu, a2.y, 8);
    a3.x += __shfl_xor_sync(0xffffffffu, a3.x, 8);
    a3.y += __shfl_xor_sync(0xffffffffu, a3.y, 8);
    if (ph == 0) {
        float sc = g_nsq[node];
        __half2 h0 = __floats2half2_rn(a0.x * sc, a0.y * sc);
        __half2 h1 = __floats2half2_rn(a1.x * sc, a1.y * sc);
        __half2 h2 = __floats2half2_rn(a2.x * sc, a2.y * sc);
        __half2 h3 = __floats2half2_rn(a3.x * sc, a3.y * sc);
        uint4 u;
        u.x = *(unsigned int*)&h0;
        u.y = *(unsigned int*)&h1;
        u.z = *(unsigned int*)&h2;
        u.w = *(unsigned int*)&h3;
        g_h1h[node * 8 + j] = u;
    }
}

__global__ void hop2_kernel(float* __restrict__ out,
                            const float* __restrict__ bias) {
    int idx = blockIdx.x * blockDim.x + threadIdx.x;
    int node = idx >> 4;
    if (node >= N_NODES) return;
    int lane = idx & 15;
    int j = lane & 7;
    int ph = lane >> 3;

    int start = g_off[node];
    int cnt   = g_deg[node];
    float2 a0 = {0,0}, a1 = {0,0}, a2 = {0,0}, a3 = {0,0};
#pragma unroll 2
    for (int i = ph; i < cnt; i += 2) {
        int s = __ldg(&g_adj[start + i]);
        uint4 v = __ldg(&g_h1h[s * 8 + j]);
        h2acc(v.x, a0); h2acc(v.y, a1); h2acc(v.z, a2); h2acc(v.w, a3);
    }
    a0.x += __shfl_xor_sync(0xffffffffu, a0.x, 8);
    a0.y += __shfl_xor_sync(0xffffffffu, a0.y, 8);
    a1.x += __shfl_xor_sync(0xffffffffu, a1.x, 8);
    a1.y += __shfl_xor_sync(0xffffffffu, a1.y, 8);
    a2.x += __shfl_xor_sync(0xffffffffu, a2.x, 8);
    a2.y += __shfl_xor_sync(0xffffffffu, a2.y, 8);
    a3.x += __shfl_xor_sync(0xffffffffu, a3.x, 8);
    a3.y += __shfl_xor_sync(0xffffffffu, a3.y, 8);
    if (ph == 0) {
        float sc = g_norm[node];
        const float4* b4 = (const float4*)bias;
        float4 b0 = b4[j * 2], b1 = b4[j * 2 + 1];
        float4 o0, o1;
        o0.x = a0.x * sc + b0.x;  o0.y = a0.y * sc + b0.y;
        o0.z = a1.x * sc + b0.z;  o0.w = a1.y * sc + b0.w;
        o1.x = a2.x * sc + b1.x;  o1.y = a2.y * sc + b1.y;
        o1.z = a3.x * sc + b1.z;  o1.w = a3.y * sc + b1.w;
        float4* out4 = (float4*)out;
        out4[node * 16 + j * 2]     = o0;
        out4[node * 16 + j * 2 + 1] = o1;
    }
}

// ----------------------------------------------------------------------------
extern "C" void kernel_launch(void* const* d_in, const int* in_sizes, int n_in,
                              void* d_out, int out_size) {
    const int*   src    = (const int*)  d_in[0];
    const int*   dst    = (const int*)  d_in[1];
    const float* feat   = (const float*)d_in[2];
    const float* weight = (const float*)d_in[3];
    const float* bias   = (const float*)d_in[4];
    float*       out    = (float*)d_out;

    const int E = in_sizes[0];

    void* deg_ptr;
    cudaGetSymbolAddress(&deg_ptr, g_deg);
    cudaMemsetAsync(deg_ptr, 0, N_NODES * sizeof(int));

    deg_kernel<<<(E / 4 + 255) / 256, 256>>>(dst, E);
    norm_kernel<<<(N_NODES + 255) / 256, 256>>>();

    scan1_kernel<<<N_SCANB, SCAN_B>>>();
    scan2_kernel<<<1, 128>>>();
    scan3_kernel<<<(N_NODES + 255) / 256, 256>>>();
    fill_kernel<<<(E + 255) / 256, 256>>>(src, dst, E);

    gemm_kernel<<<(N_NODES + 63) / 64, 256>>>(feat, weight);

    int hop_threads = N_NODES * 16;
    int hop_blocks  = (hop_threads + 255) / 256;
    hop1_kernel<<<hop_blocks, 256>>>();
    hop2_kernel<<<hop_blocks, 256>>>(out, bias);
}